// round 11
// baseline (speedup 1.0000x reference)
#include <cuda_runtime.h>
#include <math.h>
#include <stdint.h>

#define HIDDEN   2048
#define HEADS    16
#define HEAD_DIM 128
#define HALF_DIM 64
#define BATCH    2
#define SQ       2048
#define SK       2048
#define MROWS    (BATCH * SQ)   // 4096

// ---------------- scratch (device globals; no allocation allowed) ----------------
__device__ float g_Q[BATCH * SQ * HIDDEN];
__device__ float g_K[BATCH * SK * HIDDEN];
__device__ float g_V[BATCH * SK * HIDDEN];
__device__ float g_O[BATCH * SQ * HIDDEN];
__device__ float g_xr[BATCH * SQ * HIDDEN];     // x rounded to tf32 grid
__device__ float g_er[BATCH * SK * HIDDEN];     // enc rounded
__device__ float g_Wqr[HIDDEN * HIDDEN];
__device__ float g_Wkr[HIDDEN * HIDDEN];
__device__ float g_Wvr[HIDDEN * HIDDEN];
__device__ float g_Wor[HIDDEN * HIDDEN];
__device__ float g_cos[SK * HALF_DIM];
__device__ float g_sin[SK * HALF_DIM];

// ================= helpers =================
__device__ __forceinline__ uint32_t smem_u32(const void* p) {
    uint32_t a;
    asm("{ .reg .u64 t; cvta.to.shared.u64 t, %1; cvt.u32.u64 %0, t; }" : "=r"(a) : "l"(p));
    return a;
}
__device__ __forceinline__ void cp16(uint32_t dst, const void* src) {
    asm volatile("cp.async.cg.shared.global [%0], [%1], 16;" :: "r"(dst), "l"(src));
}
__device__ __forceinline__ float to_tf32(float x) {
    float y;
    asm("cvt.rna.tf32.f32 %0, %1;" : "=f"(y) : "f"(x));
    return y;
}
__device__ __forceinline__ void mma_tf32(float* c, const float* a, const float* b) {
    asm volatile(
        "mma.sync.aligned.m16n8k8.row.col.f32.tf32.tf32.f32 "
        "{%0,%1,%2,%3}, {%4,%5,%6,%7}, {%8,%9}, {%0,%1,%2,%3};"
        : "+f"(c[0]), "+f"(c[1]), "+f"(c[2]), "+f"(c[3])
        : "f"(a[0]), "f"(a[1]), "f"(a[2]), "f"(a[3]),
          "f"(b[0]), "f"(b[1]));
}

// ---------------- elementwise round-to-tf32 (inputs pre-conditioning) ------------
__global__ void round_tf32_kernel(const float* __restrict__ in, float* __restrict__ out,
                                  long n4) {
    long i = (long)blockIdx.x * blockDim.x + threadIdx.x;
    if (i >= n4) return;
    float4 v = *(const float4*)(in + i * 4);
    v.x = to_tf32(v.x); v.y = to_tf32(v.y);
    v.z = to_tf32(v.z); v.w = to_tf32(v.w);
    *(float4*)(out + i * 4) = v;
}

// ---------------- RoPE table ----------------
__global__ void rope_table_kernel() {
    int i = blockIdx.x * blockDim.x + threadIdx.x;
    if (i >= SK * HALF_DIM) return;
    int s = i / HALF_DIM;
    int f = i - s * HALF_DIM;
    double inv = pow(10000.0, -(double)f / (double)HALF_DIM);
    double ang = (double)s * inv;
    g_cos[i] = (float)cos(ang);
    g_sin[i] = (float)sin(ang);
}

// ================= tf32 mma.sync GEMM: C[M,N] = A[M,K] * B[N,K]^T ===============
// Inputs MUST already lie on the tf32 grid (HW truncation is then exact).
// CTA tile 256x128, BK=32, 512 threads (16 warps: 4M x 4N, warp tile 64x32),
// 2-stage cp.async.
#define GM_TM 256
#define GM_TN 128
#define GM_TK 32
#define GM_LDS 36
#define GM_ASTG (GM_TM * GM_LDS)              // 9216 floats
#define GM_BSTG (GM_TN * GM_LDS)              // 4608 floats
#define GM_SMEM (2 * (GM_ASTG + GM_BSTG) * 4) // 110592 bytes

__global__ __launch_bounds__(512, 1) void gemm_mma_kernel(
    const float* __restrict__ A, const float* __restrict__ Bm,
    float* __restrict__ C, int M, int N, int K, int round_out)
{
    extern __shared__ float sm[];
    float* As = sm;                           // [2][256][36]
    float* Bs = sm + 2 * GM_ASTG;             // [2][128][36]

    const int tid = threadIdx.x;
    const int wid = tid >> 5;
    const int lane = tid & 31;
    const int qr = lane >> 2;
    const int qc = lane & 3;
    const int m0 = blockIdx.y * GM_TM;
    const int n0 = blockIdx.x * GM_TN;
    const int wm = (wid >> 2) * 64;           // 4 warps along M
    const int wn = (wid & 3) * 32;            // 4 warps along N

    const uint32_t sa = smem_u32(As);
    const uint32_t sb = smem_u32(Bs);

    float acc[4][4][4];
#pragma unroll
    for (int i = 0; i < 4; i++)
#pragma unroll
        for (int j = 0; j < 4; j++)
#pragma unroll
            for (int t = 0; t < 4; t++) acc[i][j][t] = 0.f;

    auto load_stage = [&](int st, int kk) {
        uint32_t ab = sa + st * GM_ASTG * 4;
        uint32_t bb = sb + st * GM_BSTG * 4;
#pragma unroll
        for (int c = 0; c < 4; c++) {         // A: 2048 chunks / 512 threads
            int e = tid + c * 512;
            int r = e >> 3, cx = e & 7;
            cp16(ab + r * 144 + cx * 16, A + (size_t)(m0 + r) * K + kk + cx * 4);
        }
#pragma unroll
        for (int c = 0; c < 2; c++) {         // B: 1024 chunks / 512 threads
            int e = tid + c * 512;
            int r = e >> 3, cx = e & 7;
            cp16(bb + r * 144 + cx * 16, Bm + (size_t)(n0 + r) * K + kk + cx * 4);
        }
    };

    const int ITERS = K / GM_TK;   // 64
    load_stage(0, 0);
    asm volatile("cp.async.commit_group;");

    for (int it = 0; it < ITERS; it++) {
        if (it + 1 < ITERS) {
            load_stage((it + 1) & 1, (it + 1) * GM_TK);
            asm volatile("cp.async.commit_group;");
            asm volatile("cp.async.wait_group 1;" ::: "memory");
        } else {
            asm volatile("cp.async.wait_group 0;" ::: "memory");
        }
        __syncthreads();

        const float* at = As + (it & 1) * GM_ASTG;
        const float* bt = Bs + (it & 1) * GM_BSTG;

#pragma unroll
        for (int s = 0; s < 4; s++) {
            int kb = s * 8;
            float af[4][4], bf[4][2];
#pragma unroll
            for (int i = 0; i < 4; i++) {
                const float* p = at + (wm + i * 16 + qr) * GM_LDS + kb + qc;
                af[i][0] = p[0];
                af[i][1] = p[8 * GM_LDS];
                af[i][2] = p[4];
                af[i][3] = p[8 * GM_LDS + 4];
            }
#pragma unroll
            for (int j = 0; j < 4; j++) {
                const float* p = bt + (wn + j * 8 + qr) * GM_LDS + kb + qc;
                bf[j][0] = p[0];
                bf[j][1] = p[4];
            }
#pragma unroll
            for (int i = 0; i < 4; i++)
#pragma unroll
                for (int j = 0; j < 4; j++)
                    mma_tf32(acc[i][j], af[i], bf[j]);
        }
        __syncthreads();
    }

#pragma unroll
    for (int i = 0; i < 4; i++) {
        int rlo = m0 + wm + i * 16 + qr;
#pragma unroll
        for (int j = 0; j < 4; j++) {
            int col = n0 + wn + j * 8 + qc * 2;
            float4 v = make_float4(acc[i][j][0], acc[i][j][1], acc[i][j][2], acc[i][j][3]);
            if (round_out) {
                v.x = to_tf32(v.x); v.y = to_tf32(v.y);
                v.z = to_tf32(v.z); v.w = to_tf32(v.w);
            }
            *(float2*)(C + (size_t)rlo * N + col)       = make_float2(v.x, v.y);
            *(float2*)(C + (size_t)(rlo + 8) * N + col) = make_float2(v.z, v.w);
        }
    }
}

// ---------------- RoPE apply: rotate + round to tf32 grid ------------------------
__global__ void rope_apply_kernel(float* __restrict__ buf, int S, long total_pairs) {
    long i = (long)blockIdx.x * blockDim.x + threadIdx.x;
    if (i >= total_pairs) return;
    int f = (int)(i & (HALF_DIM - 1));
    long t = i >> 6;
    int s = (int)((t / HEADS) % S);
    float c  = g_cos[s * HALF_DIM + f];
    float sn = g_sin[s * HALF_DIM + f];
    float2* p = (float2*)(buf + t * (size_t)HEAD_DIM) + f;
    float2 xv = *p;
    float2 ov;
    ov.x = to_tf32(xv.x * c - xv.y * sn);
    ov.y = to_tf32(xv.x * sn + xv.y * c);
    *p = ov;
}

// ================= flash attention via tf32 mma.sync =============================
// Q/K pre-rounded by rope; V pre-rounded by projection epilogue; P rounded at exp.
// Inner loops contain NO conversions.
#define FB_BM   128
#define FB_BN   64
#define FB_QKS  132
#define FB_PS   68
#define FB_QF   (128 * FB_QKS)
#define FB_KF   (64 * FB_QKS)
#define FB_VF   (64 * FB_QKS)
#define FB_PF   (128 * FB_PS)
#define FB_SMEM ((FB_QF + 2 * FB_KF + FB_VF + FB_PF) * 4)   // 203776 bytes

__global__ __launch_bounds__(256, 1) void flash_mma_kernel(const int* __restrict__ mask) {
    extern __shared__ float sm[];
    float* Qs  = sm;
    float* Ks0 = Qs + FB_QF;
    float* Ks1 = Ks0 + FB_KF;
    float* Vs  = Ks1 + FB_KF;
    float* Ps  = Vs + FB_VF;
    __shared__ int msAll[SK];

    const int bh = blockIdx.x;
    const int b  = bh / HEADS;
    const int h  = bh - b * HEADS;
    const int q0 = blockIdx.y * FB_BM;
    const int tid  = threadIdx.x;
    const int wid  = tid >> 5;
    const int lane = tid & 31;
    const int qr = lane >> 2;
    const int qc = lane & 3;
    const int wm = wid * 16;
    const float rscale = 0.08838834764831845f;

    const uint32_t sQ  = smem_u32(Qs);
    const uint32_t sK0 = smem_u32(Ks0);
    const uint32_t sK1 = smem_u32(Ks1);
    const uint32_t sV  = smem_u32(Vs);

    const size_t headQ  = ((size_t)(b * SQ + q0) * HEADS + h) * HEAD_DIM;
    const size_t headKV = ((size_t)(b * SK) * HEADS + h) * HEAD_DIM;
    const size_t rowStride = (size_t)HEADS * HEAD_DIM;   // 2048

    auto load_K = [&](int kt) {
        uint32_t base = (kt & 1) ? sK1 : sK0;
#pragma unroll
        for (int c = 0; c < 8; c++) {
            int e = tid + c * 256;
            int r = e >> 5, d4 = (e & 31) * 4;
            cp16(base + (r * FB_QKS + d4) * 4,
                 g_K + headKV + (size_t)(kt * FB_BN + r) * rowStride + d4);
        }
    };
    auto load_V = [&](int kt) {
#pragma unroll
        for (int c = 0; c < 8; c++) {
            int e = tid + c * 256;
            int r = e >> 5, d4 = (e & 31) * 4;
            cp16(sV + (r * FB_QKS + d4) * 4,
                 g_V + headKV + (size_t)(kt * FB_BN + r) * rowStride + d4);
        }
    };

    // ---- prologue: {Q, K0} group, {V0} group, mask ----
#pragma unroll
    for (int c = 0; c < 16; c++) {
        int e = tid + c * 256;
        int r = e >> 5, d4 = (e & 31) * 4;
        cp16(sQ + (r * FB_QKS + d4) * 4, g_Q + headQ + (size_t)r * rowStride + d4);
    }
    load_K(0);
    asm volatile("cp.async.commit_group;");
    load_V(0);
    asm volatile("cp.async.commit_group;");
    for (int i = tid; i < SK; i += 256) msAll[i] = mask[b * SK + i];

    asm volatile("cp.async.wait_group 1;" ::: "memory");   // Q + K0 ready
    __syncthreads();

    float m0v = -1e30f, m1v = -1e30f;
    float l0 = 0.f, l1 = 0.f;
    float Oacc[16][4];
#pragma unroll
    for (int n = 0; n < 16; n++)
#pragma unroll
        for (int t = 0; t < 4; t++) Oacc[n][t] = 0.f;

    const int NIT = SK / FB_BN;   // 32

    for (int it = 0; it < NIT; it++) {
        const int kO = it * FB_BN;
        const float* Kc = (it & 1) ? Ks1 : Ks0;

        if (it + 1 < NIT) {
            load_K(it + 1);
            asm volatile("cp.async.commit_group;");   // pending: {V(it), K(it+1)}
        }

        // ===== S phase: S[16 x 64] = Q_band * K^T (no cvt; inputs pre-rounded) ====
        float sacc[8][4];
#pragma unroll
        for (int j = 0; j < 8; j++)
#pragma unroll
            for (int t = 0; t < 4; t++) sacc[j][t] = 0.f;

#pragma unroll
        for (int ks = 0; ks < 16; ks++) {
            int kb = ks * 8;
            float a[4];
            const float* ap = Qs + (wm + qr) * FB_QKS + kb + qc;
            a[0] = ap[0];
            a[1] = ap[8 * FB_QKS];
            a[2] = ap[4];
            a[3] = ap[8 * FB_QKS + 4];
#pragma unroll
            for (int j = 0; j < 8; j++) {
                const float* bp = Kc + (j * 8 + qr) * FB_QKS + kb + qc;
                float bfr[2];
                bfr[0] = bp[0];
                bfr[1] = bp[4];
                mma_tf32(sacc[j], a, bfr);
            }
        }

        // ===== softmax =====
        float mx0 = -1e30f, mx1 = -1e30f;
#pragma unroll
        for (int j = 0; j < 8; j++) {
            int c0 = j * 8 + 2 * qc;
            int k0m = msAll[kO + c0];
            int k1m = msAll[kO + c0 + 1];
            float v0 = k0m ? sacc[j][0] * rscale : -1e30f;
            float v1 = k1m ? sacc[j][1] * rscale : -1e30f;
            float v2 = k0m ? sacc[j][2] * rscale : -1e30f;
            float v3 = k1m ? sacc[j][3] * rscale : -1e30f;
            sacc[j][0] = v0; sacc[j][1] = v1; sacc[j][2] = v2; sacc[j][3] = v3;
            mx0 = fmaxf(mx0, fmaxf(v0, v1));
            mx1 = fmaxf(mx1, fmaxf(v2, v3));
        }
        mx0 = fmaxf(mx0, __shfl_xor_sync(0xffffffffu, mx0, 1));
        mx0 = fmaxf(mx0, __shfl_xor_sync(0xffffffffu, mx0, 2));
        mx1 = fmaxf(mx1, __shfl_xor_sync(0xffffffffu, mx1, 1));
        mx1 = fmaxf(mx1, __shfl_xor_sync(0xffffffffu, mx1, 2));

        float mn0 = fmaxf(m0v, mx0);
        float mn1 = fmaxf(m1v, mx1);
        float corr0 = expf(m0v - mn0);
        float corr1 = expf(m1v - mn1);
        m0v = mn0; m1v = mn1;

        float sum0 = 0.f, sum1 = 0.f;
#pragma unroll
        for (int j = 0; j < 8; j++) {
            float p0 = to_tf32(expf(sacc[j][0] - mn0));
            float p1 = to_tf32(expf(sacc[j][1] - mn0));
            float p2 = to_tf32(expf(sacc[j][2] - mn1));
            float p3 = to_tf32(expf(sacc[j][3] - mn1));
            sum0 += p0 + p1;
            sum1 += p2 + p3;
            int c0 = j * 8 + 2 * qc;
            *(float2*)&Ps[(wm + qr) * FB_PS + c0]     = make_float2(p0, p1);
            *(float2*)&Ps[(wm + qr + 8) * FB_PS + c0] = make_float2(p2, p3);
        }
        sum0 += __shfl_xor_sync(0xffffffffu, sum0, 1);
        sum0 += __shfl_xor_sync(0xffffffffu, sum0, 2);
        sum1 += __shfl_xor_sync(0xffffffffu, sum1, 1);
        sum1 += __shfl_xor_sync(0xffffffffu, sum1, 2);
        l0 = l0 * corr0 + sum0;
        l1 = l1 * corr1 + sum1;

#pragma unroll
        for (int n = 0; n < 16; n++) {
            Oacc[n][0] *= corr0; Oacc[n][1] *= corr0;
            Oacc[n][2] *= corr1; Oacc[n][3] *= corr1;
        }
        __syncwarp();

        if (it + 1 < NIT) {
            asm volatile("cp.async.wait_group 1;" ::: "memory");   // V(it) ready
        } else {
            asm volatile("cp.async.wait_group 0;" ::: "memory");
        }
        __syncthreads();

        // ===== PV phase: O_band += P_band * V (no cvt; P/V pre-rounded) =====
#pragma unroll
        for (int ks = 0; ks < 8; ks++) {
            int kb = ks * 8;
            float a[4];
            const float* ap = Ps + (wm + qr) * FB_PS + kb + qc;
            a[0] = ap[0];
            a[1] = ap[8 * FB_PS];
            a[2] = ap[4];
            a[3] = ap[8 * FB_PS + 4];
#pragma unroll
            for (int n = 0; n < 16; n++) {
                const float* bp = Vs + (kb + qc) * FB_QKS + n * 8 + qr;
                float bfr[2];
                bfr[0] = bp[0];
                bfr[1] = bp[4 * FB_QKS];
                mma_tf32(Oacc[n], a, bfr);
            }
        }
        __syncthreads();   // all warps done with Vs

        if (it + 1 < NIT) {
            load_V(it + 1);
            asm volatile("cp.async.commit_group;");   // pending: {K(it+1), V(it+1)}
            asm volatile("cp.async.wait_group 1;" ::: "memory");   // K(it+1) ready
            __syncthreads();
        }
    }

    // ---- epilogue: O /= l, round to tf32 grid (feeds final GEMM raw) ----
    float inv0 = 1.f / l0;
    float inv1 = 1.f / l1;
    const int row0 = q0 + wm + qr;
    float* d0 = g_O + ((size_t)(b * SQ + row0) * HEADS + h) * HEAD_DIM;
    float* d1 = d0 + 8 * rowStride;
#pragma unroll
    for (int n = 0; n < 16; n++) {
        int col = n * 8 + 2 * qc;
        *(float2*)(d0 + col) = make_float2(to_tf32(Oacc[n][0] * inv0),
                                           to_tf32(Oacc[n][1] * inv0));
        *(float2*)(d1 + col) = make_float2(to_tf32(Oacc[n][2] * inv1),
                                           to_tf32(Oacc[n][3] * inv1));
    }
}

// ---------------- launch ---------------------------------------------------------
extern "C" void kernel_launch(void* const* d_in, const int* in_sizes, int n_in,
                              void* d_out, int out_size) {
    const float* x    = (const float*)d_in[0];
    const float* enc  = (const float*)d_in[1];
    const int*   mask = (const int*)d_in[2];
    const float* Wq   = (const float*)d_in[3];
    const float* Wk   = (const float*)d_in[4];
    const float* Wv   = (const float*)d_in[5];
    const float* Wo   = (const float*)d_in[6];
    float* out = (float*)d_out;

    float *q, *k, *v, *o, *xr, *er, *wqr, *wkr, *wvr, *wor;
    cudaGetSymbolAddress((void**)&q,  g_Q);
    cudaGetSymbolAddress((void**)&k,  g_K);
    cudaGetSymbolAddress((void**)&v,  g_V);
    cudaGetSymbolAddress((void**)&o,  g_O);
    cudaGetSymbolAddress((void**)&xr, g_xr);
    cudaGetSymbolAddress((void**)&er, g_er);
    cudaGetSymbolAddress((void**)&wqr, g_Wqr);
    cudaGetSymbolAddress((void**)&wkr, g_Wkr);
    cudaGetSymbolAddress((void**)&wvr, g_Wvr);
    cudaGetSymbolAddress((void**)&wor, g_Wor);

    rope_table_kernel<<<(SK * HALF_DIM + 255) / 256, 256>>>();

    // pre-round all GEMM inputs to the tf32 grid
    const long nAct = (long)BATCH * SQ * HIDDEN / 4;
    const long nW   = (long)HIDDEN * HIDDEN / 4;
    round_tf32_kernel<<<(unsigned)((nAct + 255) / 256), 256>>>(x,   xr, nAct);
    round_tf32_kernel<<<(unsigned)((nAct + 255) / 256), 256>>>(enc, er, nAct);
    round_tf32_kernel<<<(unsigned)((nW + 255) / 256), 256>>>(Wq, wqr, nW);
    round_tf32_kernel<<<(unsigned)((nW + 255) / 256), 256>>>(Wk, wkr, nW);
    round_tf32_kernel<<<(unsigned)((nW + 255) / 256), 256>>>(Wv, wvr, nW);
    round_tf32_kernel<<<(unsigned)((nW + 255) / 256), 256>>>(Wo, wor, nW);

    cudaFuncSetAttribute(gemm_mma_kernel,
                         cudaFuncAttributeMaxDynamicSharedMemorySize, GM_SMEM);
    dim3 gg(HIDDEN / GM_TN, MROWS / GM_TM);   // (16, 16)
    gemm_mma_kernel<<<gg, 512, GM_SMEM>>>(xr, wqr, q, MROWS, HIDDEN, HIDDEN, 0);
    gemm_mma_kernel<<<gg, 512, GM_SMEM>>>(er, wkr, k, MROWS, HIDDEN, HIDDEN, 0);
    gemm_mma_kernel<<<gg, 512, GM_SMEM>>>(er, wvr, v, MROWS, HIDDEN, HIDDEN, 1);

    long pairs = (long)BATCH * SQ * HEADS * HALF_DIM;
    int rb = (int)((pairs + 255) / 256);
    rope_apply_kernel<<<rb, 256>>>(q, SQ, pairs);
    rope_apply_kernel<<<rb, 256>>>(k, SK, pairs);

    cudaFuncSetAttribute(flash_mma_kernel,
                         cudaFuncAttributeMaxDynamicSharedMemorySize, FB_SMEM);
    dim3 ga(BATCH * HEADS, SQ / FB_BM);   // (32, 16)
    flash_mma_kernel<<<ga, 256, FB_SMEM>>>(mask);

    gemm_mma_kernel<<<gg, 512, GM_SMEM>>>(o, wor, out, MROWS, HIDDEN, HIDDEN, 0);
}

// round 13
// speedup vs baseline: 1.0303x; 1.0303x over previous
#include <cuda_runtime.h>
#include <math.h>
#include <stdint.h>

#define HIDDEN   2048
#define HEADS    16
#define HEAD_DIM 128
#define HALF_DIM 64
#define BATCH    2
#define SQ       2048
#define SK       2048
#define MROWS    (BATCH * SQ)   // 4096

// ---------------- scratch (device globals; no allocation allowed) ----------------
__device__ float g_Q[BATCH * SQ * HIDDEN];
__device__ float g_K[BATCH * SK * HIDDEN];
__device__ float g_V[BATCH * SK * HIDDEN];
__device__ float g_O[BATCH * SQ * HIDDEN];
__device__ float g_xr[BATCH * SQ * HIDDEN];     // x rounded to tf32 grid
__device__ float g_er[BATCH * SK * HIDDEN];     // enc rounded
__device__ float g_Wqr[HIDDEN * HIDDEN];
__device__ float g_Wkr[HIDDEN * HIDDEN];
__device__ float g_Wvr[HIDDEN * HIDDEN];
__device__ float g_Wor[HIDDEN * HIDDEN];
__device__ float g_cos[SK * HALF_DIM];
__device__ float g_sin[SK * HALF_DIM];

// ================= helpers =================
__device__ __forceinline__ uint32_t smem_u32(const void* p) {
    uint32_t a;
    asm("{ .reg .u64 t; cvta.to.shared.u64 t, %1; cvt.u32.u64 %0, t; }" : "=r"(a) : "l"(p));
    return a;
}
__device__ __forceinline__ void cp16(uint32_t dst, const void* src) {
    asm volatile("cp.async.cg.shared.global [%0], [%1], 16;" :: "r"(dst), "l"(src));
}
__device__ __forceinline__ float to_tf32(float x) {
    float y;
    asm("cvt.rna.tf32.f32 %0, %1;" : "=f"(y) : "f"(x));
    return y;
}
__device__ __forceinline__ void mma_tf32(float* c, const float* a, const float* b) {
    asm volatile(
        "mma.sync.aligned.m16n8k8.row.col.f32.tf32.tf32.f32 "
        "{%0,%1,%2,%3}, {%4,%5,%6,%7}, {%8,%9}, {%0,%1,%2,%3};"
        : "+f"(c[0]), "+f"(c[1]), "+f"(c[2]), "+f"(c[3])
        : "f"(a[0]), "f"(a[1]), "f"(a[2]), "f"(a[3]),
          "f"(b[0]), "f"(b[1]));
}

// ---------------- elementwise round-to-tf32 (inputs pre-conditioning) ------------
__global__ void round_tf32_kernel(const float* __restrict__ in, float* __restrict__ out,
                                  long n4) {
    long i = (long)blockIdx.x * blockDim.x + threadIdx.x;
    if (i >= n4) return;
    float4 v = *(const float4*)(in + i * 4);
    v.x = to_tf32(v.x); v.y = to_tf32(v.y);
    v.z = to_tf32(v.z); v.w = to_tf32(v.w);
    *(float4*)(out + i * 4) = v;
}

// ---------------- RoPE table ----------------
__global__ void rope_table_kernel() {
    int i = blockIdx.x * blockDim.x + threadIdx.x;
    if (i >= SK * HALF_DIM) return;
    int s = i / HALF_DIM;
    int f = i - s * HALF_DIM;
    double inv = pow(10000.0, -(double)f / (double)HALF_DIM);
    double ang = (double)s * inv;
    g_cos[i] = (float)cos(ang);
    g_sin[i] = (float)sin(ang);
}

// ================= tf32 mma.sync GEMM: C[M,N] = A[M,K] * B[N,K]^T ===============
// Inputs MUST already lie on the tf32 grid (HW truncation is then exact).
// CTA tile 128x128, BK=32, 8 warps (warp tile 32x64), 2-stage cp.async.
// __launch_bounds__(256, 2): cap regs at 128 so TWO CTAs co-reside per SM.
#define GM_TM 128
#define GM_TN 128
#define GM_TK 32
#define GM_LDS 36
#define GM_STG (GM_TM * GM_LDS)
#define GM_SMEM (4 * GM_STG * 4)   // 73728 bytes

__global__ __launch_bounds__(256, 2) void gemm_mma_kernel(
    const float* __restrict__ A, const float* __restrict__ Bm,
    float* __restrict__ C, int M, int N, int K, int round_out)
{
    extern __shared__ float sm[];
    float* As = sm;
    float* Bs = sm + 2 * GM_STG;

    const int tid = threadIdx.x;
    const int wid = tid >> 5;
    const int lane = tid & 31;
    const int qr = lane >> 2;
    const int qc = lane & 3;
    const int m0 = blockIdx.y * GM_TM;
    const int n0 = blockIdx.x * GM_TN;
    const int wm = (wid & 3) * 32;
    const int wn = (wid >> 2) * 64;

    const uint32_t sa = smem_u32(As);
    const uint32_t sb = smem_u32(Bs);

    float acc[2][8][4];
#pragma unroll
    for (int i = 0; i < 2; i++)
#pragma unroll
        for (int j = 0; j < 8; j++)
#pragma unroll
            for (int t = 0; t < 4; t++) acc[i][j][t] = 0.f;

    auto load_stage = [&](int st, int kk) {
        uint32_t ab = sa + st * GM_STG * 4;
        uint32_t bb = sb + st * GM_STG * 4;
#pragma unroll
        for (int c = 0; c < 4; c++) {
            int e = tid + c * 256;
            int r = e >> 3, cx = e & 7;
            cp16(ab + r * 144 + cx * 16, A + (size_t)(m0 + r) * K + kk + cx * 4);
        }
#pragma unroll
        for (int c = 0; c < 4; c++) {
            int e = tid + c * 256;
            int r = e >> 3, cx = e & 7;
            cp16(bb + r * 144 + cx * 16, Bm + (size_t)(n0 + r) * K + kk + cx * 4);
        }
    };

    const int ITERS = K / GM_TK;
    load_stage(0, 0);
    asm volatile("cp.async.commit_group;");

    for (int it = 0; it < ITERS; it++) {
        if (it + 1 < ITERS) {
            load_stage((it + 1) & 1, (it + 1) * GM_TK);
            asm volatile("cp.async.commit_group;");
            asm volatile("cp.async.wait_group 1;" ::: "memory");
        } else {
            asm volatile("cp.async.wait_group 0;" ::: "memory");
        }
        __syncthreads();

        const float* at = As + (it & 1) * GM_STG;
        const float* bt = Bs + (it & 1) * GM_STG;

#pragma unroll
        for (int s = 0; s < 4; s++) {
            int kb = s * 8;
            float af[2][4], bf[8][2];
#pragma unroll
            for (int i = 0; i < 2; i++) {
                const float* p = at + (wm + i * 16 + qr) * GM_LDS + kb + qc;
                af[i][0] = p[0];
                af[i][1] = p[8 * GM_LDS];
                af[i][2] = p[4];
                af[i][3] = p[8 * GM_LDS + 4];
            }
#pragma unroll
            for (int j = 0; j < 8; j++) {
                const float* p = bt + (wn + j * 8 + qr) * GM_LDS + kb + qc;
                bf[j][0] = p[0];
                bf[j][1] = p[4];
            }
#pragma unroll
            for (int i = 0; i < 2; i++)
#pragma unroll
                for (int j = 0; j < 8; j++)
                    mma_tf32(acc[i][j], af[i], bf[j]);
        }
        __syncthreads();
    }

#pragma unroll
    for (int i = 0; i < 2; i++) {
        int rlo = m0 + wm + i * 16 + qr;
#pragma unroll
        for (int j = 0; j < 8; j++) {
            int col = n0 + wn + j * 8 + qc * 2;
            float4 v = make_float4(acc[i][j][0], acc[i][j][1], acc[i][j][2], acc[i][j][3]);
            if (round_out) {
                v.x = to_tf32(v.x); v.y = to_tf32(v.y);
                v.z = to_tf32(v.z); v.w = to_tf32(v.w);
            }
            *(float2*)(C + (size_t)rlo * N + col)       = make_float2(v.x, v.y);
            *(float2*)(C + (size_t)(rlo + 8) * N + col) = make_float2(v.z, v.w);
        }
    }
}

// ---------------- RoPE apply: rotate + round to tf32 grid ------------------------
__global__ void rope_apply_kernel(float* __restrict__ buf, int S, long total_pairs) {
    long i = (long)blockIdx.x * blockDim.x + threadIdx.x;
    if (i >= total_pairs) return;
    int f = (int)(i & (HALF_DIM - 1));
    long t = i >> 6;
    int s = (int)((t / HEADS) % S);
    float c  = g_cos[s * HALF_DIM + f];
    float sn = g_sin[s * HALF_DIM + f];
    float2* p = (float2*)(buf + t * (size_t)HEAD_DIM) + f;
    float2 xv = *p;
    float2 ov;
    ov.x = to_tf32(xv.x * c - xv.y * sn);
    ov.y = to_tf32(xv.x * sn + xv.y * c);
    *p = ov;
}

// ================= flash attention via tf32 mma.sync =============================
// Q/K pre-rounded by rope; V pre-rounded by projection epilogue; P rounded at exp.
// Inner loops contain NO conversions.
#define FB_BM   128
#define FB_BN   64
#define FB_QKS  132
#define FB_PS   68
#define FB_QF   (128 * FB_QKS)
#define FB_KF   (64 * FB_QKS)
#define FB_VF   (64 * FB_QKS)
#define FB_PF   (128 * FB_PS)
#define FB_SMEM ((FB_QF + 2 * FB_KF + FB_VF + FB_PF) * 4)   // 203776 bytes

__global__ __launch_bounds__(256, 1) void flash_mma_kernel(const int* __restrict__ mask) {
    extern __shared__ float sm[];
    float* Qs  = sm;
    float* Ks0 = Qs + FB_QF;
    float* Ks1 = Ks0 + FB_KF;
    float* Vs  = Ks1 + FB_KF;
    float* Ps  = Vs + FB_VF;
    __shared__ int msAll[SK];

    const int bh = blockIdx.x;
    const int b  = bh / HEADS;
    const int h  = bh - b * HEADS;
    const int q0 = blockIdx.y * FB_BM;
    const int tid  = threadIdx.x;
    const int wid  = tid >> 5;
    const int lane = tid & 31;
    const int qr = lane >> 2;
    const int qc = lane & 3;
    const int wm = wid * 16;
    const float rscale = 0.08838834764831845f;

    const uint32_t sQ  = smem_u32(Qs);
    const uint32_t sK0 = smem_u32(Ks0);
    const uint32_t sK1 = smem_u32(Ks1);
    const uint32_t sV  = smem_u32(Vs);

    const size_t headQ  = ((size_t)(b * SQ + q0) * HEADS + h) * HEAD_DIM;
    const size_t headKV = ((size_t)(b * SK) * HEADS + h) * HEAD_DIM;
    const size_t rowStride = (size_t)HEADS * HEAD_DIM;   // 2048

    auto load_K = [&](int kt) {
        uint32_t base = (kt & 1) ? sK1 : sK0;
#pragma unroll
        for (int c = 0; c < 8; c++) {
            int e = tid + c * 256;
            int r = e >> 5, d4 = (e & 31) * 4;
            cp16(base + (r * FB_QKS + d4) * 4,
                 g_K + headKV + (size_t)(kt * FB_BN + r) * rowStride + d4);
        }
    };
    auto load_V = [&](int kt) {
#pragma unroll
        for (int c = 0; c < 8; c++) {
            int e = tid + c * 256;
            int r = e >> 5, d4 = (e & 31) * 4;
            cp16(sV + (r * FB_QKS + d4) * 4,
                 g_V + headKV + (size_t)(kt * FB_BN + r) * rowStride + d4);
        }
    };

    // ---- prologue: {Q, K0} group, {V0} group, mask ----
#pragma unroll
    for (int c = 0; c < 16; c++) {
        int e = tid + c * 256;
        int r = e >> 5, d4 = (e & 31) * 4;
        cp16(sQ + (r * FB_QKS + d4) * 4, g_Q + headQ + (size_t)r * rowStride + d4);
    }
    load_K(0);
    asm volatile("cp.async.commit_group;");
    load_V(0);
    asm volatile("cp.async.commit_group;");
    for (int i = tid; i < SK; i += 256) msAll[i] = mask[b * SK + i];

    asm volatile("cp.async.wait_group 1;" ::: "memory");   // Q + K0 ready
    __syncthreads();

    float m0v = -1e30f, m1v = -1e30f;
    float l0 = 0.f, l1 = 0.f;
    float Oacc[16][4];
#pragma unroll
    for (int n = 0; n < 16; n++)
#pragma unroll
        for (int t = 0; t < 4; t++) Oacc[n][t] = 0.f;

    const int NIT = SK / FB_BN;   // 32

    for (int it = 0; it < NIT; it++) {
        const int kO = it * FB_BN;
        const float* Kc = (it & 1) ? Ks1 : Ks0;

        if (it + 1 < NIT) {
            load_K(it + 1);
            asm volatile("cp.async.commit_group;");   // pending: {V(it), K(it+1)}
        }

        // ===== S phase: S[16 x 64] = Q_band * K^T (no cvt; inputs pre-rounded) ====
        float sacc[8][4];
#pragma unroll
        for (int j = 0; j < 8; j++)
#pragma unroll
            for (int t = 0; t < 4; t++) sacc[j][t] = 0.f;

#pragma unroll
        for (int ks = 0; ks < 16; ks++) {
            int kb = ks * 8;
            float a[4];
            const float* ap = Qs + (wm + qr) * FB_QKS + kb + qc;
            a[0] = ap[0];
            a[1] = ap[8 * FB_QKS];
            a[2] = ap[4];
            a[3] = ap[8 * FB_QKS + 4];
#pragma unroll
            for (int j = 0; j < 8; j++) {
                const float* bp = Kc + (j * 8 + qr) * FB_QKS + kb + qc;
                float bfr[2];
                bfr[0] = bp[0];
                bfr[1] = bp[4];
                mma_tf32(sacc[j], a, bfr);
            }
        }

        // ===== softmax =====
        float mx0 = -1e30f, mx1 = -1e30f;
#pragma unroll
        for (int j = 0; j < 8; j++) {
            int c0 = j * 8 + 2 * qc;
            int k0m = msAll[kO + c0];
            int k1m = msAll[kO + c0 + 1];
            float v0 = k0m ? sacc[j][0] * rscale : -1e30f;
            float v1 = k1m ? sacc[j][1] * rscale : -1e30f;
            float v2 = k0m ? sacc[j][2] * rscale : -1e30f;
            float v3 = k1m ? sacc[j][3] * rscale : -1e30f;
            sacc[j][0] = v0; sacc[j][1] = v1; sacc[j][2] = v2; sacc[j][3] = v3;
            mx0 = fmaxf(mx0, fmaxf(v0, v1));
            mx1 = fmaxf(mx1, fmaxf(v2, v3));
        }
        mx0 = fmaxf(mx0, __shfl_xor_sync(0xffffffffu, mx0, 1));
        mx0 = fmaxf(mx0, __shfl_xor_sync(0xffffffffu, mx0, 2));
        mx1 = fmaxf(mx1, __shfl_xor_sync(0xffffffffu, mx1, 1));
        mx1 = fmaxf(mx1, __shfl_xor_sync(0xffffffffu, mx1, 2));

        float mn0 = fmaxf(m0v, mx0);
        float mn1 = fmaxf(m1v, mx1);
        float corr0 = expf(m0v - mn0);
        float corr1 = expf(m1v - mn1);
        m0v = mn0; m1v = mn1;

        float sum0 = 0.f, sum1 = 0.f;
#pragma unroll
        for (int j = 0; j < 8; j++) {
            float p0 = to_tf32(expf(sacc[j][0] - mn0));
            float p1 = to_tf32(expf(sacc[j][1] - mn0));
            float p2 = to_tf32(expf(sacc[j][2] - mn1));
            float p3 = to_tf32(expf(sacc[j][3] - mn1));
            sum0 += p0 + p1;
            sum1 += p2 + p3;
            int c0 = j * 8 + 2 * qc;
            *(float2*)&Ps[(wm + qr) * FB_PS + c0]     = make_float2(p0, p1);
            *(float2*)&Ps[(wm + qr + 8) * FB_PS + c0] = make_float2(p2, p3);
        }
        sum0 += __shfl_xor_sync(0xffffffffu, sum0, 1);
        sum0 += __shfl_xor_sync(0xffffffffu, sum0, 2);
        sum1 += __shfl_xor_sync(0xffffffffu, sum1, 1);
        sum1 += __shfl_xor_sync(0xffffffffu, sum1, 2);
        l0 = l0 * corr0 + sum0;
        l1 = l1 * corr1 + sum1;

#pragma unroll
        for (int n = 0; n < 16; n++) {
            Oacc[n][0] *= corr0; Oacc[n][1] *= corr0;
            Oacc[n][2] *= corr1; Oacc[n][3] *= corr1;
        }
        __syncwarp();

        if (it + 1 < NIT) {
            asm volatile("cp.async.wait_group 1;" ::: "memory");   // V(it) ready
        } else {
            asm volatile("cp.async.wait_group 0;" ::: "memory");
        }
        __syncthreads();

        // ===== PV phase: O_band += P_band * V (no cvt; P/V pre-rounded) =====
#pragma unroll
        for (int ks = 0; ks < 8; ks++) {
            int kb = ks * 8;
            float a[4];
            const float* ap = Ps + (wm + qr) * FB_PS + kb + qc;
            a[0] = ap[0];
            a[1] = ap[8 * FB_PS];
            a[2] = ap[4];
            a[3] = ap[8 * FB_PS + 4];
#pragma unroll
            for (int n = 0; n < 16; n++) {
                const float* bp = Vs + (kb + qc) * FB_QKS + n * 8 + qr;
                float bfr[2];
                bfr[0] = bp[0];
                bfr[1] = bp[4 * FB_QKS];
                mma_tf32(Oacc[n], a, bfr);
            }
        }
        __syncthreads();   // all warps done with Vs

        if (it + 1 < NIT) {
            load_V(it + 1);
            asm volatile("cp.async.commit_group;");   // pending: {K(it+1), V(it+1)}
            asm volatile("cp.async.wait_group 1;" ::: "memory");   // K(it+1) ready
            __syncthreads();
        }
    }

    // ---- epilogue: O /= l, round to tf32 grid (feeds final GEMM raw) ----
    float inv0 = 1.f / l0;
    float inv1 = 1.f / l1;
    const int row0 = q0 + wm + qr;
    float* d0 = g_O + ((size_t)(b * SQ + row0) * HEADS + h) * HEAD_DIM;
    float* d1 = d0 + 8 * rowStride;
#pragma unroll
    for (int n = 0; n < 16; n++) {
        int col = n * 8 + 2 * qc;
        *(float2*)(d0 + col) = make_float2(to_tf32(Oacc[n][0] * inv0),
                                           to_tf32(Oacc[n][1] * inv0));
        *(float2*)(d1 + col) = make_float2(to_tf32(Oacc[n][2] * inv1),
                                           to_tf32(Oacc[n][3] * inv1));
    }
}

// ---------------- launch ---------------------------------------------------------
extern "C" void kernel_launch(void* const* d_in, const int* in_sizes, int n_in,
                              void* d_out, int out_size) {
    const float* x    = (const float*)d_in[0];
    const float* enc  = (const float*)d_in[1];
    const int*   mask = (const int*)d_in[2];
    const float* Wq   = (const float*)d_in[3];
    const float* Wk   = (const float*)d_in[4];
    const float* Wv   = (const float*)d_in[5];
    const float* Wo   = (const float*)d_in[6];
    float* out = (float*)d_out;

    float *q, *k, *v, *o, *xr, *er, *wqr, *wkr, *wvr, *wor;
    cudaGetSymbolAddress((void**)&q,  g_Q);
    cudaGetSymbolAddress((void**)&k,  g_K);
    cudaGetSymbolAddress((void**)&v,  g_V);
    cudaGetSymbolAddress((void**)&o,  g_O);
    cudaGetSymbolAddress((void**)&xr, g_xr);
    cudaGetSymbolAddress((void**)&er, g_er);
    cudaGetSymbolAddress((void**)&wqr, g_Wqr);
    cudaGetSymbolAddress((void**)&wkr, g_Wkr);
    cudaGetSymbolAddress((void**)&wvr, g_Wvr);
    cudaGetSymbolAddress((void**)&wor, g_Wor);

    rope_table_kernel<<<(SK * HALF_DIM + 255) / 256, 256>>>();

    // pre-round all GEMM inputs to the tf32 grid
    const long nAct = (long)BATCH * SQ * HIDDEN / 4;
    const long nW   = (long)HIDDEN * HIDDEN / 4;
    round_tf32_kernel<<<(unsigned)((nAct + 255) / 256), 256>>>(x,   xr, nAct);
    round_tf32_kernel<<<(unsigned)((nAct + 255) / 256), 256>>>(enc, er, nAct);
    round_tf32_kernel<<<(unsigned)((nW + 255) / 256), 256>>>(Wq, wqr, nW);
    round_tf32_kernel<<<(unsigned)((nW + 255) / 256), 256>>>(Wk, wkr, nW);
    round_tf32_kernel<<<(unsigned)((nW + 255) / 256), 256>>>(Wv, wvr, nW);
    round_tf32_kernel<<<(unsigned)((nW + 255) / 256), 256>>>(Wo, wor, nW);

    cudaFuncSetAttribute(gemm_mma_kernel,
                         cudaFuncAttributeMaxDynamicSharedMemorySize, GM_SMEM);
    dim3 gg(HIDDEN / GM_TN, MROWS / GM_TM);   // (16, 32)
    gemm_mma_kernel<<<gg, 256, GM_SMEM>>>(xr, wqr, q, MROWS, HIDDEN, HIDDEN, 0);
    gemm_mma_kernel<<<gg, 256, GM_SMEM>>>(er, wkr, k, MROWS, HIDDEN, HIDDEN, 0);
    gemm_mma_kernel<<<gg, 256, GM_SMEM>>>(er, wvr, v, MROWS, HIDDEN, HIDDEN, 1);

    long pairs = (long)BATCH * SQ * HEADS * HALF_DIM;
    int rb = (int)((pairs + 255) / 256);
    rope_apply_kernel<<<rb, 256>>>(q, SQ, pairs);
    rope_apply_kernel<<<rb, 256>>>(k, SK, pairs);

    cudaFuncSetAttribute(flash_mma_kernel,
                         cudaFuncAttributeMaxDynamicSharedMemorySize, FB_SMEM);
    dim3 ga(BATCH * HEADS, SQ / FB_BM);   // (32, 16)
    flash_mma_kernel<<<ga, 256, FB_SMEM>>>(mask);

    gemm_mma_kernel<<<gg, 256, GM_SMEM>>>(o, wor, out, MROWS, HIDDEN, HIDDEN, 0);
}

// round 15
// speedup vs baseline: 1.6959x; 1.6461x over previous
#include <cuda_runtime.h>
#include <cuda_fp16.h>
#include <math.h>
#include <stdint.h>

#define HIDDEN   2048
#define HEADS    16
#define HEAD_DIM 128
#define HALF_DIM 64
#define BATCH    2
#define SQ       2048
#define SK       2048
#define MROWS    (BATCH * SQ)   // 4096

// ---------------- scratch (device globals; no allocation allowed) ----------------
__device__ float  g_Q[BATCH * SQ * HIDDEN];    // fp32 GEMM outputs (pre-RoPE)
__device__ float  g_K[BATCH * SK * HIDDEN];
__device__ float  g_V[BATCH * SK * HIDDEN];
__device__ __half g_Qh[BATCH * SQ * HIDDEN];   // post-RoPE half
__device__ __half g_Kh[BATCH * SK * HIDDEN];
__device__ __half g_Vth[BATCH * HEADS * HEAD_DIM * SK];  // V transposed [b,h,d,t]
__device__ __half g_Oh[BATCH * SQ * HIDDEN];   // attention output half
__device__ __half g_xh[BATCH * SQ * HIDDEN];
__device__ __half g_eh[BATCH * SK * HIDDEN];
__device__ __half g_Wqh[HIDDEN * HIDDEN];
__device__ __half g_Wkh[HIDDEN * HIDDEN];
__device__ __half g_Wvh[HIDDEN * HIDDEN];
__device__ __half g_Woh[HIDDEN * HIDDEN];
__device__ float  g_cos[SK * HALF_DIM];
__device__ float  g_sin[SK * HALF_DIM];

// ================= helpers =================
__device__ __forceinline__ uint32_t smem_u32(const void* p) {
    uint32_t a;
    asm("{ .reg .u64 t; cvta.to.shared.u64 t, %1; cvt.u32.u64 %0, t; }" : "=r"(a) : "l"(p));
    return a;
}
__device__ __forceinline__ void cp16(uint32_t dst, const void* src) {
    asm volatile("cp.async.cg.shared.global [%0], [%1], 16;" :: "r"(dst), "l"(src));
}
__device__ __forceinline__ void mma_f16(float* c, const uint32_t* a, const uint32_t* b) {
    asm volatile(
        "mma.sync.aligned.m16n8k16.row.col.f32.f16.f16.f32 "
        "{%0,%1,%2,%3}, {%4,%5,%6,%7}, {%8,%9}, {%0,%1,%2,%3};"
        : "+f"(c[0]), "+f"(c[1]), "+f"(c[2]), "+f"(c[3])
        : "r"(a[0]), "r"(a[1]), "r"(a[2]), "r"(a[3]),
          "r"(b[0]), "r"(b[1]));
}
__device__ __forceinline__ uint32_t ldh2(const __half* p) {
    return *(const uint32_t*)p;
}

// ---------------- fp32 -> fp16 elementwise ----------------
__global__ void to_half_kernel(const float* __restrict__ in, __half* __restrict__ out,
                               long n4) {
    long i = (long)blockIdx.x * blockDim.x + threadIdx.x;
    if (i >= n4) return;
    float4 v = *(const float4*)(in + i * 4);
    __half2* o = (__half2*)(out + i * 4);
    o[0] = __floats2half2_rn(v.x, v.y);
    o[1] = __floats2half2_rn(v.z, v.w);
}

// ---------------- RoPE table ----------------
__global__ void rope_table_kernel() {
    int i = blockIdx.x * blockDim.x + threadIdx.x;
    if (i >= SK * HALF_DIM) return;
    int s = i / HALF_DIM;
    int f = i - s * HALF_DIM;
    double inv = pow(10000.0, -(double)f / (double)HALF_DIM);
    double ang = (double)s * inv;
    g_cos[i] = (float)cos(ang);
    g_sin[i] = (float)sin(ang);
}

// ================= fp16 mma.sync GEMM: C[M,N] = A[M,K] * B[N,K]^T ===============
// CTA tile 128x128, BK=32 (2 x k16), 8 warps (warp tile 32x64), 2-stage cp.async.
#define GM_TM 128
#define GM_TN 128
#define GM_TK 32
#define GM_LDSH 40                            // smem row stride in halfs (80B)
#define GM_STGH (GM_TM * GM_LDSH)             // halfs per tile stage (5120)
#define GM_SMEM (4 * GM_STGH * 2)             // A/B x 2 stages, bytes (40960)

__global__ __launch_bounds__(256, 2) void gemm_mma_kernel(
    const __half* __restrict__ A, const __half* __restrict__ Bm,
    float* __restrict__ C, int M, int N, int K)
{
    extern __shared__ __half smh[];
    __half* As = smh;                          // [2][128][40]
    __half* Bs = smh + 2 * GM_STGH;            // [2][128][40]

    const int tid = threadIdx.x;
    const int wid = tid >> 5;
    const int lane = tid & 31;
    const int qr = lane >> 2;
    const int qc = lane & 3;
    const int m0 = blockIdx.y * GM_TM;
    const int n0 = blockIdx.x * GM_TN;
    const int wm = (wid & 3) * 32;
    const int wn = (wid >> 2) * 64;

    const uint32_t sa = smem_u32(As);
    const uint32_t sb = smem_u32(Bs);

    float acc[2][8][4];
#pragma unroll
    for (int i = 0; i < 2; i++)
#pragma unroll
        for (int j = 0; j < 8; j++)
#pragma unroll
            for (int t = 0; t < 4; t++) acc[i][j][t] = 0.f;

    // stage loader: 128 rows A + 128 rows B, each row = 4 x 16B chunks (8 halfs)
    auto load_stage = [&](int st, int kk) {
        uint32_t ab = sa + st * GM_STGH * 2;
        uint32_t bb = sb + st * GM_STGH * 2;
#pragma unroll
        for (int c = 0; c < 2; c++) {          // A: 512 chunks / 256 threads
            int e = tid + c * 256;
            int r = e >> 2, cx = e & 3;
            cp16(ab + r * 80 + cx * 16, A + (size_t)(m0 + r) * K + kk + cx * 8);
        }
#pragma unroll
        for (int c = 0; c < 2; c++) {          // B: 512 chunks
            int e = tid + c * 256;
            int r = e >> 2, cx = e & 3;
            cp16(bb + r * 80 + cx * 16, Bm + (size_t)(n0 + r) * K + kk + cx * 8);
        }
    };

    const int ITERS = K / GM_TK;   // 64
    load_stage(0, 0);
    asm volatile("cp.async.commit_group;");

    for (int it = 0; it < ITERS; it++) {
        if (it + 1 < ITERS) {
            load_stage((it + 1) & 1, (it + 1) * GM_TK);
            asm volatile("cp.async.commit_group;");
            asm volatile("cp.async.wait_group 1;" ::: "memory");
        } else {
            asm volatile("cp.async.wait_group 0;" ::: "memory");
        }
        __syncthreads();

        const __half* at = As + (it & 1) * GM_STGH;
        const __half* bt = Bs + (it & 1) * GM_STGH;

#pragma unroll
        for (int s = 0; s < 2; s++) {          // two k16 steps per BK=32
            int kb = s * 16;
            uint32_t af[2][4], bf[8][2];
#pragma unroll
            for (int i = 0; i < 2; i++) {
                const __half* p = at + (wm + i * 16 + qr) * GM_LDSH + kb + 2 * qc;
                af[i][0] = ldh2(p);
                af[i][1] = ldh2(p + 8 * GM_LDSH);
                af[i][2] = ldh2(p + 8);
                af[i][3] = ldh2(p + 8 * GM_LDSH + 8);
            }
#pragma unroll
            for (int j = 0; j < 8; j++) {
                const __half* p = bt + (wn + j * 8 + qr) * GM_LDSH + kb + 2 * qc;
                bf[j][0] = ldh2(p);
                bf[j][1] = ldh2(p + 8);
            }
#pragma unroll
            for (int i = 0; i < 2; i++)
#pragma unroll
                for (int j = 0; j < 8; j++)
                    mma_f16(acc[i][j], af[i], bf[j]);
        }
        __syncthreads();
    }

#pragma unroll
    for (int i = 0; i < 2; i++) {
        int rlo = m0 + wm + i * 16 + qr;
#pragma unroll
        for (int j = 0; j < 8; j++) {
            int col = n0 + wn + j * 8 + qc * 2;
            *(float2*)(C + (size_t)rlo * N + col)       = make_float2(acc[i][j][0], acc[i][j][1]);
            *(float2*)(C + (size_t)(rlo + 8) * N + col) = make_float2(acc[i][j][2], acc[i][j][3]);
        }
    }
}

// ---------------- RoPE apply: fp32 in, rotate, fp16 out --------------------------
__global__ void rope_apply_kernel(const float* __restrict__ src, __half* __restrict__ dst,
                                  int S, long total_pairs) {
    long i = (long)blockIdx.x * blockDim.x + threadIdx.x;
    if (i >= total_pairs) return;
    int f = (int)(i & (HALF_DIM - 1));
    long t = i >> 6;
    int s = (int)((t / HEADS) % S);
    float c  = g_cos[s * HALF_DIM + f];
    float sn = g_sin[s * HALF_DIM + f];
    const float2 xv = ((const float2*)(src + t * (size_t)HEAD_DIM))[f];
    float ox = xv.x * c - xv.y * sn;
    float oy = xv.x * sn + xv.y * c;
    ((__half2*)(dst + t * (size_t)HEAD_DIM))[f] = __floats2half2_rn(ox, oy);
}

// ---------------- V transpose: fp32 [b,t,h,d] -> fp16 [b,h,d,t] ------------------
__global__ void transpose_v_kernel() {
    __shared__ float tile[32][33];
    const int bh = blockIdx.x;            // b*HEADS + h
    const int b  = bh / HEADS;
    const int h  = bh - b * HEADS;
    const int t0 = blockIdx.y * 32;
    const int d0 = blockIdx.z * 32;
    const int tx = threadIdx.x;           // 0..31
    const int ty = threadIdx.y;           // 0..7

    for (int i = ty; i < 32; i += 8)
        tile[i][tx] = g_V[((size_t)(b * SK + t0 + i) * HEADS + h) * HEAD_DIM + d0 + tx];
    __syncthreads();
    for (int i = ty; i < 32; i += 8)
        g_Vth[((size_t)bh * HEAD_DIM + d0 + i) * SK + t0 + tx] = __float2half_rn(tile[tx][i]);
}

// ================= flash attention via fp16 mma.sync =============================
// CTA: 128 q-rows of one (b,h). 64-key tiles. 8 warps, 16-row q band each.
// K double-buffered; V pre-transposed [d][t] half; P stored half2 at exp time.
#define FB_BM   128
#define FB_BN   64
#define FB_QKS  136     // Q/K row stride (halfs)
#define FB_VS   72      // Vt row stride (halfs)
#define FB_PS2  72      // P row stride (halfs)
#define FB_QFH  (128 * FB_QKS)
#define FB_KFH  (64 * FB_QKS)
#define FB_VFH  (128 * FB_VS)
#define FB_PFH  (128 * FB_PS2)
#define FB_SMEM ((FB_QFH + 2 * FB_KFH + FB_VFH + FB_PFH) * 2)   // 106496 bytes

__global__ __launch_bounds__(256, 1) void flash_mma_kernel(const int* __restrict__ mask) {
    extern __shared__ __half smh[];
    __half* Qs  = smh;
    __half* Ks0 = Qs + FB_QFH;
    __half* Ks1 = Ks0 + FB_KFH;
    __half* Vt  = Ks1 + FB_KFH;
    __half* Ps  = Vt + FB_VFH;
    __shared__ int msAll[SK];

    const int bh = blockIdx.x;
    const int b  = bh / HEADS;
    const int h  = bh - b * HEADS;
    const int q0 = blockIdx.y * FB_BM;
    const int tid  = threadIdx.x;
    const int wid  = tid >> 5;
    const int lane = tid & 31;
    const int qr = lane >> 2;
    const int qc = lane & 3;
    const int wm = wid * 16;
    const float rscale = 0.08838834764831845f;

    const uint32_t sQ  = smem_u32(Qs);
    const uint32_t sK0 = smem_u32(Ks0);
    const uint32_t sK1 = smem_u32(Ks1);
    const uint32_t sV  = smem_u32(Vt);

    const size_t headQ  = ((size_t)(b * SQ + q0) * HEADS + h) * HEAD_DIM;
    const size_t headKV = ((size_t)(b * SK) * HEADS + h) * HEAD_DIM;
    const size_t headVt = (size_t)bh * HEAD_DIM * SK;
    const size_t rowStride = (size_t)HEADS * HEAD_DIM;   // 2048

    auto load_K = [&](int kt) {
        uint32_t base = (kt & 1) ? sK1 : sK0;
#pragma unroll
        for (int c = 0; c < 4; c++) {          // 64 rows x 16 chunks = 1024
            int e = tid + c * 256;
            int r = e >> 4, cx = e & 15;
            cp16(base + (r * FB_QKS + cx * 8) * 2,
                 g_Kh + headKV + (size_t)(kt * FB_BN + r) * rowStride + cx * 8);
        }
    };
    auto load_V = [&](int kt) {
#pragma unroll
        for (int c = 0; c < 4; c++) {          // 128 d-rows x 8 chunks = 1024
            int e = tid + c * 256;
            int r = e >> 3, cx = e & 7;
            cp16(sV + (r * FB_VS + cx * 8) * 2,
                 g_Vth + headVt + (size_t)r * SK + kt * FB_BN + cx * 8);
        }
    };

    // ---- prologue: {Q, K0} group, {V0} group, mask ----
#pragma unroll
    for (int c = 0; c < 8; c++) {              // Q: 128 rows x 16 chunks = 2048
        int e = tid + c * 256;
        int r = e >> 4, cx = e & 15;
        cp16(sQ + (r * FB_QKS + cx * 8) * 2,
             g_Qh + headQ + (size_t)r * rowStride + cx * 8);
    }
    load_K(0);
    asm volatile("cp.async.commit_group;");
    load_V(0);
    asm volatile("cp.async.commit_group;");
    for (int i = tid; i < SK; i += 256) msAll[i] = mask[b * SK + i];

    asm volatile("cp.async.wait_group 1;" ::: "memory");   // Q + K0 ready
    __syncthreads();

    float m0v = -1e30f, m1v = -1e30f;
    float l0 = 0.f, l1 = 0.f;
    float Oacc[16][4];
#pragma unroll
    for (int n = 0; n < 16; n++)
#pragma unroll
        for (int t = 0; t < 4; t++) Oacc[n][t] = 0.f;

    const int NIT = SK / FB_BN;   // 32

    for (int it = 0; it < NIT; it++) {
        const int kO = it * FB_BN;
        const __half* Kc = (it & 1) ? Ks1 : Ks0;

        if (it + 1 < NIT) {
            load_K(it + 1);
            asm volatile("cp.async.commit_group;");   // pending: {V(it), K(it+1)}
        }

        // ===== S phase: S[16 x 64] = Q_band * K^T, 8 x k16 steps =====
        float sacc[8][4];
#pragma unroll
        for (int j = 0; j < 8; j++)
#pragma unroll
            for (int t = 0; t < 4; t++) sacc[j][t] = 0.f;

#pragma unroll
        for (int ks = 0; ks < 8; ks++) {
            int kb = ks * 16;
            uint32_t a[4];
            const __half* ap = Qs + (wm + qr) * FB_QKS + kb + 2 * qc;
            a[0] = ldh2(ap);
            a[1] = ldh2(ap + 8 * FB_QKS);
            a[2] = ldh2(ap + 8);
            a[3] = ldh2(ap + 8 * FB_QKS + 8);
#pragma unroll
            for (int j = 0; j < 8; j++) {
                const __half* bp = Kc + (j * 8 + qr) * FB_QKS + kb + 2 * qc;
                uint32_t bfr[2];
                bfr[0] = ldh2(bp);
                bfr[1] = ldh2(bp + 8);
                mma_f16(sacc[j], a, bfr);
            }
        }

        // ===== softmax =====
        float mx0 = -1e30f, mx1 = -1e30f;
#pragma unroll
        for (int j = 0; j < 8; j++) {
            int c0 = j * 8 + 2 * qc;
            int k0m = msAll[kO + c0];
            int k1m = msAll[kO + c0 + 1];
            float v0 = k0m ? sacc[j][0] * rscale : -1e30f;
            float v1 = k1m ? sacc[j][1] * rscale : -1e30f;
            float v2 = k0m ? sacc[j][2] * rscale : -1e30f;
            float v3 = k1m ? sacc[j][3] * rscale : -1e30f;
            sacc[j][0] = v0; sacc[j][1] = v1; sacc[j][2] = v2; sacc[j][3] = v3;
            mx0 = fmaxf(mx0, fmaxf(v0, v1));
            mx1 = fmaxf(mx1, fmaxf(v2, v3));
        }
        mx0 = fmaxf(mx0, __shfl_xor_sync(0xffffffffu, mx0, 1));
        mx0 = fmaxf(mx0, __shfl_xor_sync(0xffffffffu, mx0, 2));
        mx1 = fmaxf(mx1, __shfl_xor_sync(0xffffffffu, mx1, 1));
        mx1 = fmaxf(mx1, __shfl_xor_sync(0xffffffffu, mx1, 2));

        float mn0 = fmaxf(m0v, mx0);
        float mn1 = fmaxf(m1v, mx1);
        float corr0 = expf(m0v - mn0);
        float corr1 = expf(m1v - mn1);
        m0v = mn0; m1v = mn1;

        float sum0 = 0.f, sum1 = 0.f;
#pragma unroll
        for (int j = 0; j < 8; j++) {
            float p0 = expf(sacc[j][0] - mn0);
            float p1 = expf(sacc[j][1] - mn0);
            float p2 = expf(sacc[j][2] - mn1);
            float p3 = expf(sacc[j][3] - mn1);
            sum0 += p0 + p1;
            sum1 += p2 + p3;
            int c0 = j * 8 + 2 * qc;
            *(__half2*)&Ps[(wm + qr) * FB_PS2 + c0]     = __floats2half2_rn(p0, p1);
            *(__half2*)&Ps[(wm + qr + 8) * FB_PS2 + c0] = __floats2half2_rn(p2, p3);
        }
        sum0 += __shfl_xor_sync(0xffffffffu, sum0, 1);
        sum0 += __shfl_xor_sync(0xffffffffu, sum0, 2);
        sum1 += __shfl_xor_sync(0xffffffffu, sum1, 1);
        sum1 += __shfl_xor_sync(0xffffffffu, sum1, 2);
        l0 = l0 * corr0 + sum0;
        l1 = l1 * corr1 + sum1;

#pragma unroll
        for (int n = 0; n < 16; n++) {
            Oacc[n][0] *= corr0; Oacc[n][1] *= corr0;
            Oacc[n][2] *= corr1; Oacc[n][3] *= corr1;
        }
        __syncwarp();

        if (it + 1 < NIT) {
            asm volatile("cp.async.wait_group 1;" ::: "memory");   // V(it) ready
        } else {
            asm volatile("cp.async.wait_group 0;" ::: "memory");
        }
        __syncthreads();

        // ===== PV phase: O_band += P_band * V, 4 x k16 steps =====
#pragma unroll
        for (int ks = 0; ks < 4; ks++) {
            int kb = ks * 16;
            uint32_t a[4];
            const __half* ap = Ps + (wm + qr) * FB_PS2 + kb + 2 * qc;
            a[0] = ldh2(ap);
            a[1] = ldh2(ap + 8 * FB_PS2);
            a[2] = ldh2(ap + 8);
            a[3] = ldh2(ap + 8 * FB_PS2 + 8);
#pragma unroll
            for (int n = 0; n < 16; n++) {
                const __half* bp = Vt + (n * 8 + qr) * FB_VS + kb + 2 * qc;
                uint32_t bfr[2];
                bfr[0] = ldh2(bp);
                bfr[1] = ldh2(bp + 8);
                mma_f16(Oacc[n], a, bfr);
            }
        }
        __syncthreads();   // all warps done with Vt

        if (it + 1 < NIT) {
            load_V(it + 1);
            asm volatile("cp.async.commit_group;");   // pending: {K(it+1), V(it+1)}
            asm volatile("cp.async.wait_group 1;" ::: "memory");   // K(it+1) ready
            __syncthreads();
        }
    }

    // ---- epilogue: O /= l, write half [b,s,h,d] ----
    float inv0 = 1.f / l0;
    float inv1 = 1.f / l1;
    const int row0 = q0 + wm + qr;
    __half* d0 = g_Oh + ((size_t)(b * SQ + row0) * HEADS + h) * HEAD_DIM;
    __half* d1 = d0 + 8 * rowStride;
#pragma unroll
    for (int n = 0; n < 16; n++) {
        int col = n * 8 + 2 * qc;
        *(__half2*)(d0 + col) = __floats2half2_rn(Oacc[n][0] * inv0, Oacc[n][1] * inv0);
        *(__half2*)(d1 + col) = __floats2half2_rn(Oacc[n][2] * inv1, Oacc[n][3] * inv1);
    }
}

// ---------------- launch ---------------------------------------------------------
extern "C" void kernel_launch(void* const* d_in, const int* in_sizes, int n_in,
                              void* d_out, int out_size) {
    const float* x    = (const float*)d_in[0];
    const float* enc  = (const float*)d_in[1];
    const int*   mask = (const int*)d_in[2];
    const float* Wq   = (const float*)d_in[3];
    const float* Wk   = (const float*)d_in[4];
    const float* Wv   = (const float*)d_in[5];
    const float* Wo   = (const float*)d_in[6];
    float* out = (float*)d_out;

    float *q, *k, *v;
    __half *qh, *kh, *oh, *xh, *eh, *wqh, *wkh, *wvh, *woh;
    cudaGetSymbolAddress((void**)&q,   g_Q);
    cudaGetSymbolAddress((void**)&k,   g_K);
    cudaGetSymbolAddress((void**)&v,   g_V);
    cudaGetSymbolAddress((void**)&qh,  g_Qh);
    cudaGetSymbolAddress((void**)&kh,  g_Kh);
    cudaGetSymbolAddress((void**)&oh,  g_Oh);
    cudaGetSymbolAddress((void**)&xh,  g_xh);
    cudaGetSymbolAddress((void**)&eh,  g_eh);
    cudaGetSymbolAddress((void**)&wqh, g_Wqh);
    cudaGetSymbolAddress((void**)&wkh, g_Wkh);
    cudaGetSymbolAddress((void**)&wvh, g_Wvh);
    cudaGetSymbolAddress((void**)&woh, g_Woh);

    rope_table_kernel<<<(SK * HALF_DIM + 255) / 256, 256>>>();

    // convert inputs to fp16
    const long nAct = (long)BATCH * SQ * HIDDEN / 4;
    const long nW   = (long)HIDDEN * HIDDEN / 4;
    to_half_kernel<<<(unsigned)((nAct + 255) / 256), 256>>>(x,   xh, nAct);
    to_half_kernel<<<(unsigned)((nAct + 255) / 256), 256>>>(enc, eh, nAct);
    to_half_kernel<<<(unsigned)((nW + 255) / 256), 256>>>(Wq, wqh, nW);
    to_half_kernel<<<(unsigned)((nW + 255) / 256), 256>>>(Wk, wkh, nW);
    to_half_kernel<<<(unsigned)((nW + 255) / 256), 256>>>(Wv, wvh, nW);
    to_half_kernel<<<(unsigned)((nW + 255) / 256), 256>>>(Wo, woh, nW);

    cudaFuncSetAttribute(gemm_mma_kernel,
                         cudaFuncAttributeMaxDynamicSharedMemorySize, GM_SMEM);
    dim3 gg(HIDDEN / GM_TN, MROWS / GM_TM);   // (16, 32)
    gemm_mma_kernel<<<gg, 256, GM_SMEM>>>(xh, wqh, q, MROWS, HIDDEN, HIDDEN);
    gemm_mma_kernel<<<gg, 256, GM_SMEM>>>(eh, wkh, k, MROWS, HIDDEN, HIDDEN);
    gemm_mma_kernel<<<gg, 256, GM_SMEM>>>(eh, wvh, v, MROWS, HIDDEN, HIDDEN);

    long pairs = (long)BATCH * SQ * HEADS * HALF_DIM;
    int rb = (int)((pairs + 255) / 256);
    rope_apply_kernel<<<rb, 256>>>(q, qh, SQ, pairs);
    rope_apply_kernel<<<rb, 256>>>(k, kh, SK, pairs);

    dim3 tg(BATCH * HEADS, SK / 32, HEAD_DIM / 32);   // (32, 64, 4)
    transpose_v_kernel<<<tg, dim3(32, 8)>>>();

    cudaFuncSetAttribute(flash_mma_kernel,
                         cudaFuncAttributeMaxDynamicSharedMemorySize, FB_SMEM);
    dim3 ga(BATCH * HEADS, SQ / FB_BM);   // (32, 16)
    flash_mma_kernel<<<ga, 256, FB_SMEM>>>(mask);

    gemm_mma_kernel<<<gg, 256, GM_SMEM>>>(oh, woh, out, MROWS, HIDDEN, HIDDEN);
}

// round 16
// speedup vs baseline: 1.8287x; 1.0783x over previous
#include <cuda_runtime.h>
#include <cuda_fp16.h>
#include <math.h>
#include <stdint.h>

#define HIDDEN   2048
#define HEADS    16
#define HEAD_DIM 128
#define HALF_DIM 64
#define BATCH    2
#define SQ       2048
#define SK       2048
#define MROWS    (BATCH * SQ)   // 4096

// ---------------- scratch (device globals; no allocation allowed) ----------------
__device__ float  g_Q[BATCH * SQ * HIDDEN];    // fp32 GEMM outputs (pre-RoPE)
__device__ float  g_K[BATCH * SK * HIDDEN];
__device__ float  g_V[BATCH * SK * HIDDEN];
__device__ __half g_Qh[BATCH * SQ * HIDDEN];   // post-RoPE half
__device__ __half g_Kh[BATCH * SK * HIDDEN];
__device__ __half g_Vth[BATCH * HEADS * HEAD_DIM * SK];  // V transposed [b,h,d,t]
__device__ __half g_Oh[BATCH * SQ * HIDDEN];   // attention output half
__device__ __half g_xh[BATCH * SQ * HIDDEN];
__device__ __half g_eh[BATCH * SK * HIDDEN];
__device__ __half g_Wqh[HIDDEN * HIDDEN];
__device__ __half g_Wkh[HIDDEN * HIDDEN];
__device__ __half g_Wvh[HIDDEN * HIDDEN];
__device__ __half g_Woh[HIDDEN * HIDDEN];
__device__ float  g_cos[SK * HALF_DIM];
__device__ float  g_sin[SK * HALF_DIM];

// ================= helpers =================
__device__ __forceinline__ uint32_t smem_u32(const void* p) {
    uint32_t a;
    asm("{ .reg .u64 t; cvta.to.shared.u64 t, %1; cvt.u32.u64 %0, t; }" : "=r"(a) : "l"(p));
    return a;
}
__device__ __forceinline__ void cp16(uint32_t dst, const void* src) {
    asm volatile("cp.async.cg.shared.global [%0], [%1], 16;" :: "r"(dst), "l"(src));
}
__device__ __forceinline__ void mma_f16(float* c, const uint32_t* a, const uint32_t* b) {
    asm volatile(
        "mma.sync.aligned.m16n8k16.row.col.f32.f16.f16.f32 "
        "{%0,%1,%2,%3}, {%4,%5,%6,%7}, {%8,%9}, {%0,%1,%2,%3};"
        : "+f"(c[0]), "+f"(c[1]), "+f"(c[2]), "+f"(c[3])
        : "r"(a[0]), "r"(a[1]), "r"(a[2]), "r"(a[3]),
          "r"(b[0]), "r"(b[1]));
}
__device__ __forceinline__ void ldmx4(uint32_t* r, uint32_t addr) {
    asm volatile("ldmatrix.sync.aligned.m8n8.x4.shared.b16 {%0,%1,%2,%3}, [%4];"
        : "=r"(r[0]), "=r"(r[1]), "=r"(r[2]), "=r"(r[3]) : "r"(addr));
}

// ---------------- fp32 -> fp16 elementwise ----------------
__global__ void to_half_kernel(const float* __restrict__ in, __half* __restrict__ out,
                               long n4) {
    long i = (long)blockIdx.x * blockDim.x + threadIdx.x;
    if (i >= n4) return;
    float4 v = *(const float4*)(in + i * 4);
    __half2* o = (__half2*)(out + i * 4);
    o[0] = __floats2half2_rn(v.x, v.y);
    o[1] = __floats2half2_rn(v.z, v.w);
}

// ---------------- RoPE table ----------------
__global__ void rope_table_kernel() {
    int i = blockIdx.x * blockDim.x + threadIdx.x;
    if (i >= SK * HALF_DIM) return;
    int s = i / HALF_DIM;
    int f = i - s * HALF_DIM;
    double inv = pow(10000.0, -(double)f / (double)HALF_DIM);
    double ang = (double)s * inv;
    g_cos[i] = (float)cos(ang);
    g_sin[i] = (float)sin(ang);
}

// ================= fp16 mma.sync GEMM: C[M,N] = A[M,K] * B[N,K]^T ===============
// CTA tile 128x128, BK=32 (2 x k16), 8 warps (warp tile 32x64), 2-stage cp.async,
// ldmatrix.x4 fragment loads.
#define GM_TM 128
#define GM_TN 128
#define GM_TK 32
#define GM_LDSH 40                            // smem row stride in halfs (80B)
#define GM_STGH (GM_TM * GM_LDSH)             // halfs per tile stage (5120)
#define GM_SMEM (4 * GM_STGH * 2)             // A/B x 2 stages, bytes (40960)

__global__ __launch_bounds__(256, 2) void gemm_mma_kernel(
    const __half* __restrict__ A, const __half* __restrict__ Bm,
    float* __restrict__ C, int M, int N, int K)
{
    extern __shared__ __half smh[];
    __half* As = smh;                          // [2][128][40]
    __half* Bs = smh + 2 * GM_STGH;            // [2][128][40]

    const int tid = threadIdx.x;
    const int wid = tid >> 5;
    const int lane = tid & 31;
    const int qr = lane >> 2;
    const int qc = lane & 3;
    const int m0 = blockIdx.y * GM_TM;
    const int n0 = blockIdx.x * GM_TN;
    const int wm = (wid & 3) * 32;
    const int wn = (wid >> 2) * 64;

    const uint32_t sa = smem_u32(As);
    const uint32_t sb = smem_u32(Bs);

    // ldmatrix per-lane row/col mapping
    const int arow = ((lane >> 3) & 1) * 8 + (lane & 7);
    const int acol = (lane >> 4) * 8;
    const int brow = (lane >> 4) * 8 + (lane & 7);
    const int bcol = ((lane >> 3) & 1) * 8;

    float acc[2][8][4];
#pragma unroll
    for (int i = 0; i < 2; i++)
#pragma unroll
        for (int j = 0; j < 8; j++)
#pragma unroll
            for (int t = 0; t < 4; t++) acc[i][j][t] = 0.f;

    auto load_stage = [&](int st, int kk) {
        uint32_t ab = sa + st * GM_STGH * 2;
        uint32_t bb = sb + st * GM_STGH * 2;
#pragma unroll
        for (int c = 0; c < 2; c++) {
            int e = tid + c * 256;
            int r = e >> 2, cx = e & 3;
            cp16(ab + r * 80 + cx * 16, A + (size_t)(m0 + r) * K + kk + cx * 8);
        }
#pragma unroll
        for (int c = 0; c < 2; c++) {
            int e = tid + c * 256;
            int r = e >> 2, cx = e & 3;
            cp16(bb + r * 80 + cx * 16, Bm + (size_t)(n0 + r) * K + kk + cx * 8);
        }
    };

    const int ITERS = K / GM_TK;   // 64
    load_stage(0, 0);
    asm volatile("cp.async.commit_group;");

    for (int it = 0; it < ITERS; it++) {
        if (it + 1 < ITERS) {
            load_stage((it + 1) & 1, (it + 1) * GM_TK);
            asm volatile("cp.async.commit_group;");
            asm volatile("cp.async.wait_group 1;" ::: "memory");
        } else {
            asm volatile("cp.async.wait_group 0;" ::: "memory");
        }
        __syncthreads();

        uint32_t aaddr = sa + (it & 1) * GM_STGH * 2 + ((wm + arow) * GM_LDSH + acol) * 2;
        uint32_t baddr = sb + (it & 1) * GM_STGH * 2 + ((wn + brow) * GM_LDSH + bcol) * 2;

#pragma unroll
        for (int s = 0; s < 2; s++) {          // two k16 steps per BK=32
            int kb = s * 16;
            uint32_t af[2][4], bf[4][4];
#pragma unroll
            for (int i = 0; i < 2; i++)
                ldmx4(af[i], aaddr + (i * 16 * GM_LDSH + kb) * 2);
#pragma unroll
            for (int j2 = 0; j2 < 4; j2++)
                ldmx4(bf[j2], baddr + (j2 * 16 * GM_LDSH + kb) * 2);
#pragma unroll
            for (int i = 0; i < 2; i++)
#pragma unroll
                for (int j = 0; j < 8; j++)
                    mma_f16(acc[i][j], af[i], &bf[j >> 1][(j & 1) * 2]);
        }
        __syncthreads();
    }

#pragma unroll
    for (int i = 0; i < 2; i++) {
        int rlo = m0 + wm + i * 16 + qr;
#pragma unroll
        for (int j = 0; j < 8; j++) {
            int col = n0 + wn + j * 8 + qc * 2;
            *(float2*)(C + (size_t)rlo * N + col)       = make_float2(acc[i][j][0], acc[i][j][1]);
            *(float2*)(C + (size_t)(rlo + 8) * N + col) = make_float2(acc[i][j][2], acc[i][j][3]);
        }
    }
}

// ---------------- RoPE apply: fp32 in, rotate, fp16 out --------------------------
__global__ void rope_apply_kernel(const float* __restrict__ src, __half* __restrict__ dst,
                                  int S, long total_pairs) {
    long i = (long)blockIdx.x * blockDim.x + threadIdx.x;
    if (i >= total_pairs) return;
    int f = (int)(i & (HALF_DIM - 1));
    long t = i >> 6;
    int s = (int)((t / HEADS) % S);
    float c  = g_cos[s * HALF_DIM + f];
    float sn = g_sin[s * HALF_DIM + f];
    const float2 xv = ((const float2*)(src + t * (size_t)HEAD_DIM))[f];
    float ox = xv.x * c - xv.y * sn;
    float oy = xv.x * sn + xv.y * c;
    ((__half2*)(dst + t * (size_t)HEAD_DIM))[f] = __floats2half2_rn(ox, oy);
}

// ---------------- V transpose: fp32 [b,t,h,d] -> fp16 [b,h,d,t] ------------------
__global__ void transpose_v_kernel() {
    __shared__ float tile[32][33];
    const int bh = blockIdx.x;
    const int b  = bh / HEADS;
    const int h  = bh - b * HEADS;
    const int t0 = blockIdx.y * 32;
    const int d0 = blockIdx.z * 32;
    const int tx = threadIdx.x;
    const int ty = threadIdx.y;

    for (int i = ty; i < 32; i += 8)
        tile[i][tx] = g_V[((size_t)(b * SK + t0 + i) * HEADS + h) * HEAD_DIM + d0 + tx];
    __syncthreads();
    for (int i = ty; i < 32; i += 8)
        g_Vth[((size_t)bh * HEAD_DIM + d0 + i) * SK + t0 + tx] = __float2half_rn(tile[tx][i]);
}

// ================= flash attention via fp16 mma.sync + ldmatrix ==================
#define FB_BM   128
#define FB_BN   64
#define FB_QKS  136     // Q/K row stride (halfs)
#define FB_VS   72      // Vt row stride (halfs)
#define FB_PS2  72      // P row stride (halfs)
#define FB_QFH  (128 * FB_QKS)
#define FB_KFH  (64 * FB_QKS)
#define FB_VFH  (128 * FB_VS)
#define FB_PFH  (128 * FB_PS2)
#define FB_SMEM ((FB_QFH + 2 * FB_KFH + FB_VFH + FB_PFH) * 2)   // 106496 bytes

__global__ __launch_bounds__(256, 1) void flash_mma_kernel(const int* __restrict__ mask) {
    extern __shared__ __half smh[];
    __half* Qs  = smh;
    __half* Ks0 = Qs + FB_QFH;
    __half* Ks1 = Ks0 + FB_KFH;
    __half* Vt  = Ks1 + FB_KFH;
    __half* Ps  = Vt + FB_VFH;
    __shared__ int msAll[SK];

    const int bh = blockIdx.x;
    const int b  = bh / HEADS;
    const int h  = bh - b * HEADS;
    const int q0 = blockIdx.y * FB_BM;
    const int tid  = threadIdx.x;
    const int wid  = tid >> 5;
    const int lane = tid & 31;
    const int qr = lane >> 2;
    const int qc = lane & 3;
    const int wm = wid * 16;
    const float rscale = 0.08838834764831845f;

    const uint32_t sQ  = smem_u32(Qs);
    const uint32_t sK0 = smem_u32(Ks0);
    const uint32_t sK1 = smem_u32(Ks1);
    const uint32_t sV  = smem_u32(Vt);
    const uint32_t sP  = smem_u32(Ps);

    const int arow = ((lane >> 3) & 1) * 8 + (lane & 7);
    const int acol = (lane >> 4) * 8;
    const int brow = (lane >> 4) * 8 + (lane & 7);
    const int bcol = ((lane >> 3) & 1) * 8;

    const size_t headQ  = ((size_t)(b * SQ + q0) * HEADS + h) * HEAD_DIM;
    const size_t headKV = ((size_t)(b * SK) * HEADS + h) * HEAD_DIM;
    const size_t headVt = (size_t)bh * HEAD_DIM * SK;
    const size_t rowStride = (size_t)HEADS * HEAD_DIM;   // 2048

    auto load_K = [&](int kt) {
        uint32_t base = (kt & 1) ? sK1 : sK0;
#pragma unroll
        for (int c = 0; c < 4; c++) {
            int e = tid + c * 256;
            int r = e >> 4, cx = e & 15;
            cp16(base + (r * FB_QKS + cx * 8) * 2,
                 g_Kh + headKV + (size_t)(kt * FB_BN + r) * rowStride + cx * 8);
        }
    };
    auto load_V = [&](int kt) {
#pragma unroll
        for (int c = 0; c < 4; c++) {
            int e = tid + c * 256;
            int r = e >> 3, cx = e & 7;
            cp16(sV + (r * FB_VS + cx * 8) * 2,
                 g_Vth + headVt + (size_t)r * SK + kt * FB_BN + cx * 8);
        }
    };

    // ---- prologue ----
#pragma unroll
    for (int c = 0; c < 8; c++) {
        int e = tid + c * 256;
        int r = e >> 4, cx = e & 15;
        cp16(sQ + (r * FB_QKS + cx * 8) * 2,
             g_Qh + headQ + (size_t)r * rowStride + cx * 8);
    }
    load_K(0);
    asm volatile("cp.async.commit_group;");
    load_V(0);
    asm volatile("cp.async.commit_group;");
    for (int i = tid; i < SK; i += 256) msAll[i] = mask[b * SK + i];

    asm volatile("cp.async.wait_group 1;" ::: "memory");
    __syncthreads();

    float m0v = -1e30f, m1v = -1e30f;
    float l0 = 0.f, l1 = 0.f;
    float Oacc[16][4];
#pragma unroll
    for (int n = 0; n < 16; n++)
#pragma unroll
        for (int t = 0; t < 4; t++) Oacc[n][t] = 0.f;

    const uint32_t qaddr = sQ + ((wm + arow) * FB_QKS + acol) * 2;
    const uint32_t paddr = sP + ((wm + arow) * FB_PS2 + acol) * 2;

    const int NIT = SK / FB_BN;   // 32

    for (int it = 0; it < NIT; it++) {
        const int kO = it * FB_BN;
        const uint32_t sKc = (it & 1) ? sK1 : sK0;
        const uint32_t kaddr = sKc + (brow * FB_QKS + bcol) * 2;

        if (it + 1 < NIT) {
            load_K(it + 1);
            asm volatile("cp.async.commit_group;");   // pending: {V(it), K(it+1)}
        }

        // ===== S phase: S[16 x 64] = Q_band * K^T, 8 x k16 steps, ldmatrix =====
        float sacc[8][4];
#pragma unroll
        for (int j = 0; j < 8; j++)
#pragma unroll
            for (int t = 0; t < 4; t++) sacc[j][t] = 0.f;

#pragma unroll
        for (int ks = 0; ks < 8; ks++) {
            int kb = ks * 16;
            uint32_t a[4];
            ldmx4(a, qaddr + kb * 2);
#pragma unroll
            for (int j2 = 0; j2 < 4; j2++) {
                uint32_t bf[4];
                ldmx4(bf, kaddr + (j2 * 16 * FB_QKS + kb) * 2);
                mma_f16(sacc[j2 * 2],     a, &bf[0]);
                mma_f16(sacc[j2 * 2 + 1], a, &bf[2]);
            }
        }

        // ===== softmax =====
        float mx0 = -1e30f, mx1 = -1e30f;
#pragma unroll
        for (int j = 0; j < 8; j++) {
            int c0 = j * 8 + 2 * qc;
            int k0m = msAll[kO + c0];
            int k1m = msAll[kO + c0 + 1];
            float v0 = k0m ? sacc[j][0] * rscale : -1e30f;
            float v1 = k1m ? sacc[j][1] * rscale : -1e30f;
            float v2 = k0m ? sacc[j][2] * rscale : -1e30f;
            float v3 = k1m ? sacc[j][3] * rscale : -1e30f;
            sacc[j][0] = v0; sacc[j][1] = v1; sacc[j][2] = v2; sacc[j][3] = v3;
            mx0 = fmaxf(mx0, fmaxf(v0, v1));
            mx1 = fmaxf(mx1, fmaxf(v2, v3));
        }
        mx0 = fmaxf(mx0, __shfl_xor_sync(0xffffffffu, mx0, 1));
        mx0 = fmaxf(mx0, __shfl_xor_sync(0xffffffffu, mx0, 2));
        mx1 = fmaxf(mx1, __shfl_xor_sync(0xffffffffu, mx1, 1));
        mx1 = fmaxf(mx1, __shfl_xor_sync(0xffffffffu, mx1, 2));

        float mn0 = fmaxf(m0v, mx0);
        float mn1 = fmaxf(m1v, mx1);
        float corr0 = expf(m0v - mn0);
        float corr1 = expf(m1v - mn1);
        m0v = mn0; m1v = mn1;

        float sum0 = 0.f, sum1 = 0.f;
#pragma unroll
        for (int j = 0; j < 8; j++) {
            float p0 = expf(sacc[j][0] - mn0);
            float p1 = expf(sacc[j][1] - mn0);
            float p2 = expf(sacc[j][2] - mn1);
            float p3 = expf(sacc[j][3] - mn1);
            sum0 += p0 + p1;
            sum1 += p2 + p3;
            int c0 = j * 8 + 2 * qc;
            *(__half2*)&Ps[(wm + qr) * FB_PS2 + c0]     = __floats2half2_rn(p0, p1);
            *(__half2*)&Ps[(wm + qr + 8) * FB_PS2 + c0] = __floats2half2_rn(p2, p3);
        }
        sum0 += __shfl_xor_sync(0xffffffffu, sum0, 1);
        sum0 += __shfl_xor_sync(0xffffffffu, sum0, 2);
        sum1 += __shfl_xor_sync(0xffffffffu, sum1, 1);
        sum1 += __shfl_xor_sync(0xffffffffu, sum1, 2);
        l0 = l0 * corr0 + sum0;
        l1 = l1 * corr1 + sum1;

#pragma unroll
        for (int n = 0; n < 16; n++) {
            Oacc[n][0] *= corr0; Oacc[n][1] *= corr0;
            Oacc[n][2] *= corr1; Oacc[n][3] *= corr1;
        }
        __syncwarp();

        if (it + 1 < NIT) {
            asm volatile("cp.async.wait_group 1;" ::: "memory");   // V(it) ready
        } else {
            asm volatile("cp.async.wait_group 0;" ::: "memory");
        }
        __syncthreads();

        // ===== PV phase: O_band += P_band * V, 4 x k16 steps, ldmatrix =====
#pragma unroll
        for (int ks = 0; ks < 4; ks++) {
            int kb = ks * 16;
            uint32_t a[4];
            ldmx4(a, paddr + kb * 2);
#pragma unroll
            for (int n2 = 0; n2 < 8; n2++) {
                uint32_t vf[4];
                ldmx4(vf, sV + ((n2 * 16 + brow) * FB_VS + bcol + kb) * 2);
                mma_f16(Oacc[n2 * 2],     a, &vf[0]);
                mma_f16(Oacc[n2 * 2 + 1], a, &vf[2]);
            }
        }
        __syncthreads();

        if (it + 1 < NIT) {
            load_V(it + 1);
            asm volatile("cp.async.commit_group;");   // pending: {K(it+1), V(it+1)}
            asm volatile("cp.async.wait_group 1;" ::: "memory");   // K(it+1) ready
            __syncthreads();
        }
    }

    // ---- epilogue ----
    float inv0 = 1.f / l0;
    float inv1 = 1.f / l1;
    const int row0 = q0 + wm + qr;
    __half* d0 = g_Oh + ((size_t)(b * SQ + row0) * HEADS + h) * HEAD_DIM;
    __half* d1 = d0 + 8 * rowStride;
#pragma unroll
    for (int n = 0; n < 16; n++) {
        int col = n * 8 + 2 * qc;
        *(__half2*)(d0 + col) = __floats2half2_rn(Oacc[n][0] * inv0, Oacc[n][1] * inv0);
        *(__half2*)(d1 + col) = __floats2half2_rn(Oacc[n][2] * inv1, Oacc[n][3] * inv1);
    }
}

// ---------------- launch ---------------------------------------------------------
extern "C" void kernel_launch(void* const* d_in, const int* in_sizes, int n_in,
                              void* d_out, int out_size) {
    const float* x    = (const float*)d_in[0];
    const float* enc  = (const float*)d_in[1];
    const int*   mask = (const int*)d_in[2];
    const float* Wq   = (const float*)d_in[3];
    const float* Wk   = (const float*)d_in[4];
    const float* Wv   = (const float*)d_in[5];
    const float* Wo   = (const float*)d_in[6];
    float* out = (float*)d_out;

    float *q, *k, *v;
    __half *qh, *kh, *oh, *xh, *eh, *wqh, *wkh, *wvh, *woh;
    cudaGetSymbolAddress((void**)&q,   g_Q);
    cudaGetSymbolAddress((void**)&k,   g_K);
    cudaGetSymbolAddress((void**)&v,   g_V);
    cudaGetSymbolAddress((void**)&qh,  g_Qh);
    cudaGetSymbolAddress((void**)&kh,  g_Kh);
    cudaGetSymbolAddress((void**)&oh,  g_Oh);
    cudaGetSymbolAddress((void**)&xh,  g_xh);
    cudaGetSymbolAddress((void**)&eh,  g_eh);
    cudaGetSymbolAddress((void**)&wqh, g_Wqh);
    cudaGetSymbolAddress((void**)&wkh, g_Wkh);
    cudaGetSymbolAddress((void**)&wvh, g_Wvh);
    cudaGetSymbolAddress((void**)&woh, g_Woh);

    rope_table_kernel<<<(SK * HALF_DIM + 255) / 256, 256>>>();

    const long nAct = (long)BATCH * SQ * HIDDEN / 4;
    const long nW   = (long)HIDDEN * HIDDEN / 4;
    to_half_kernel<<<(unsigned)((nAct + 255) / 256), 256>>>(x,   xh, nAct);
    to_half_kernel<<<(unsigned)((nAct + 255) / 256), 256>>>(enc, eh, nAct);
    to_half_kernel<<<(unsigned)((nW + 255) / 256), 256>>>(Wq, wqh, nW);
    to_half_kernel<<<(unsigned)((nW + 255) / 256), 256>>>(Wk, wkh, nW);
    to_half_kernel<<<(unsigned)((nW + 255) / 256), 256>>>(Wv, wvh, nW);
    to_half_kernel<<<(unsigned)((nW + 255) / 256), 256>>>(Wo, woh, nW);

    cudaFuncSetAttribute(gemm_mma_kernel,
                         cudaFuncAttributeMaxDynamicSharedMemorySize, GM_SMEM);
    dim3 gg(HIDDEN / GM_TN, MROWS / GM_TM);   // (16, 32)
    gemm_mma_kernel<<<gg, 256, GM_SMEM>>>(xh, wqh, q, MROWS, HIDDEN, HIDDEN);
    gemm_mma_kernel<<<gg, 256, GM_SMEM>>>(eh, wkh, k, MROWS, HIDDEN, HIDDEN);
    gemm_mma_kernel<<<gg, 256, GM_SMEM>>>(eh, wvh, v, MROWS, HIDDEN, HIDDEN);

    long pairs = (long)BATCH * SQ * HEADS * HALF_DIM;
    int rb = (int)((pairs + 255) / 256);
    rope_apply_kernel<<<rb, 256>>>(q, qh, SQ, pairs);
    rope_apply_kernel<<<rb, 256>>>(k, kh, SK, pairs);

    dim3 tg(BATCH * HEADS, SK / 32, HEAD_DIM / 32);   // (32, 64, 4)
    transpose_v_kernel<<<tg, dim3(32, 8)>>>();

    cudaFuncSetAttribute(flash_mma_kernel,
                         cudaFuncAttributeMaxDynamicSharedMemorySize, FB_SMEM);
    dim3 ga(BATCH * HEADS, SQ / FB_BM);   // (32, 16)
    flash_mma_kernel<<<ga, 256, FB_SMEM>>>(mask);

    gemm_mma_kernel<<<gg, 256, GM_SMEM>>>(oh, woh, out, MROWS, HIDDEN, HIDDEN);
}